// round 15
// baseline (speedup 1.0000x reference)
#include <cuda_runtime.h>
#include <cuda_bf16.h>
#include <math.h>
#include <stdint.h>

#define S_LEN 2048
#define HID 1280
#define NH 16
#define HD 80
#define INTER 3420
#define INTERP 3424
#define NLAYER 8
#define MERGED 5120
#define OUTDIM 3584
#define MTOK 512

// ---------------- scratch ----------------
__device__ float g_hs[S_LEN * HID];
__device__ float g_qkv[S_LEN * 3 * HID];
__device__ __nv_bfloat16 g_wqkvB[NLAYER * 3840 * HID], g_wqkvS[NLAYER * 3840 * HID];
__device__ __nv_bfloat16 g_wprojB[NLAYER * HID * HID], g_wprojS[NLAYER * HID * HID];
__device__ __nv_bfloat16 g_wguB[NLAYER * 2 * INTER * HID], g_wguS[NLAYER * 2 * INTER * HID];
__device__ __nv_bfloat16 g_wdownB[NLAYER * HID * INTERP], g_wdownS[NLAYER * HID * INTERP];
__device__ __nv_bfloat16 g_wfc1B[MERGED * MERGED], g_wfc1S[MERGED * MERGED];
__device__ __nv_bfloat16 g_wfc2B[OUTDIM * MERGED], g_wfc2S[OUTDIM * MERGED];
__device__ __nv_bfloat16 g_xB[S_LEN * HID], g_xS[S_LEN * HID];
__device__ __nv_bfloat16 g_aB[S_LEN * HID], g_aS[S_LEN * HID];
__device__ __nv_bfloat16 g_gB[S_LEN * INTERP], g_gS[S_LEN * INTERP];
__device__ uint2 g_qp[NH * 40 * S_LEN], g_kp[NH * 40 * S_LEN], g_vp[NH * (S_LEN / 2) * HD];

// ---------------- helpers ----------------
__device__ __forceinline__ void split_bf16(float x, uint16_t& b, uint16_t& s) {
    __nv_bfloat16 hb = __float2bfloat16(x);
    float r = x - __bfloat162float(hb);
    __nv_bfloat16 hs = __float2bfloat16(r);
    b = *(uint16_t*)&hb; s = *(uint16_t*)&hs;
}
__device__ __forceinline__ uint2 pack_pair(float lo, float hi) {
    uint16_t bl, sl, bh, sh;
    split_bf16(lo, bl, sl); split_bf16(hi, bh, sh);
    return make_uint2((uint32_t)bl | ((uint32_t)bh << 16), (uint32_t)sl | ((uint32_t)sh << 16));
}
__device__ __forceinline__ void store_plane2(__nv_bfloat16* B, __nv_bfloat16* S,
                                             long off, float v0, float v1) {
    uint16_t b0, s0, b1, s1;
    split_bf16(v0, b0, s0); split_bf16(v1, b1, s1);
    *(uint32_t*)(B + off) = (uint32_t)b0 | ((uint32_t)b1 << 16);
    *(uint32_t*)(S + off) = (uint32_t)s0 | ((uint32_t)s1 << 16);
}

// ---------------- elementwise ----------------
// W[L][K][N] fp32 -> planes [L][N][ldw] bf16 (transpose), uint32 writes
__global__ void __launch_bounds__(256) convT_k(const float* __restrict__ W,
                                               __nv_bfloat16* __restrict__ outB,
                                               __nv_bfloat16* __restrict__ outS,
                                               int K, int N, int ldw) {
    __shared__ float tile[32][33];
    int l = blockIdx.z;
    const float* Wl = W + (long)l * K * N;
    long obase = (long)l * N * ldw;
    int n0 = blockIdx.x * 32, k0 = blockIdx.y * 32;
    int tx = threadIdx.x & 31, ty = threadIdx.x >> 5;
    for (int i = ty; i < 32; i += 8) {
        int k = k0 + i, n = n0 + tx;
        tile[i][tx] = (k < K && n < N) ? Wl[(long)k * N + n] : 0.f;
    }
    __syncthreads();
    int kp = threadIdx.x & 15, nr = threadIdx.x >> 4;
#pragma unroll
    for (int pass = 0; pass < 2; ++pass) {
        int i = nr + pass * 16;
        int n = n0 + i, k = k0 + 2 * kp;
        if (n < N && k < K) {
            uint16_t b0, s0, b1, s1;
            split_bf16(tile[2 * kp][i], b0, s0);
            split_bf16(tile[2 * kp + 1][i], b1, s1);
            *(uint32_t*)(outB + obase + (long)n * ldw + k) = (uint32_t)b0 | ((uint32_t)b1 << 16);
            *(uint32_t*)(outS + obase + (long)n * ldw + k) = (uint32_t)s0 | ((uint32_t)s1 << 16);
        }
    }
}

// gate/up interleaved: out row 2j = gate col j, row 2j+1 = up col j
__global__ void __launch_bounds__(256) convT2_k(const float* __restrict__ Wg,
                                                const float* __restrict__ Wu,
                                                __nv_bfloat16* __restrict__ outB,
                                                __nv_bfloat16* __restrict__ outS) {
    __shared__ float tg_[32][33];
    __shared__ float tu_[32][33];
    int l = blockIdx.z;
    const float* Wgl = Wg + (long)l * HID * INTER;
    const float* Wul = Wu + (long)l * HID * INTER;
    long obase = (long)l * 2 * INTER * HID;
    int n0 = blockIdx.x * 32, k0 = blockIdx.y * 32;
    int tx = threadIdx.x & 31, ty = threadIdx.x >> 5;
    for (int i = ty; i < 32; i += 8) {
        int k = k0 + i, n = n0 + tx;
        float gv = (k < HID && n < INTER) ? Wgl[(long)k * INTER + n] : 0.f;
        float uv = (k < HID && n < INTER) ? Wul[(long)k * INTER + n] : 0.f;
        tg_[i][tx] = gv; tu_[i][tx] = uv;
    }
    __syncthreads();
    int kp = threadIdx.x & 15, nr = threadIdx.x >> 4;
#pragma unroll
    for (int pass = 0; pass < 2; ++pass) {
        int i = nr + pass * 16;
        int n = n0 + i, k = k0 + 2 * kp;
        if (n < INTER && k < HID) {
            uint16_t b0, s0, b1, s1;
            split_bf16(tg_[2 * kp][i], b0, s0);
            split_bf16(tg_[2 * kp + 1][i], b1, s1);
            *(uint32_t*)(outB + obase + (long)(2 * n) * HID + k) = (uint32_t)b0 | ((uint32_t)b1 << 16);
            *(uint32_t*)(outS + obase + (long)(2 * n) * HID + k) = (uint32_t)s0 | ((uint32_t)s1 << 16);
            split_bf16(tu_[2 * kp][i], b0, s0);
            split_bf16(tu_[2 * kp + 1][i], b1, s1);
            *(uint32_t*)(outB + obase + (long)(2 * n + 1) * HID + k) = (uint32_t)b0 | ((uint32_t)b1 << 16);
            *(uint32_t*)(outS + obase + (long)(2 * n + 1) * HID + k) = (uint32_t)s0 | ((uint32_t)s1 << 16);
        }
    }
}

// warp-per-row rmsnorm -> planes
template <bool MERGER>
__global__ void __launch_bounds__(256) rmsnorm_plane_k(const float* __restrict__ x,
                                                       const float* __restrict__ w,
                                                       __nv_bfloat16* __restrict__ yB,
                                                       __nv_bfloat16* __restrict__ yS) {
    int row = blockIdx.x * 8 + (threadIdx.x >> 5);
    int lane = threadIdx.x & 31;
    const float* xr = x + (long)row * HID;
    float2 v[20];
    float ss = 0.f;
#pragma unroll
    for (int i = 0; i < 20; ++i) {
        v[i] = *(const float2*)(xr + i * 64 + 2 * lane);
        ss += v[i].x * v[i].x + v[i].y * v[i].y;
    }
#pragma unroll
    for (int o = 16; o > 0; o >>= 1) ss += __shfl_xor_sync(0xffffffffu, ss, o);
    float inv = rsqrtf(ss / (float)HID + 1e-6f);
    long base = MERGER ? ((long)(row >> 2) * MERGED + (row & 3) * HID) : ((long)row * HID);
#pragma unroll
    for (int i = 0; i < 20; ++i) {
        int col = i * 64 + 2 * lane;
        float2 wv = *(const float2*)(w + col);
        store_plane2(yB, yS, base + col, v[i].x * inv * wv.x, v[i].y * inv * wv.y);
    }
}

// rope + pack q,k k-major over d; v pairs over kv
__global__ void __launch_bounds__(256) rope_pack_k(const float* __restrict__ qkv,
                                                   const float* __restrict__ cs,
                                                   const float* __restrict__ sn,
                                                   uint2* __restrict__ Qp,
                                                   uint2* __restrict__ Kp,
                                                   uint2* __restrict__ Vp) {
    extern __shared__ float smf[];
    float (*sq)[81] = (float(*)[81])smf;
    float (*sk)[81] = (float(*)[81])(smf + 64 * 81);
    float (*sv)[81] = (float(*)[81])(smf + 2 * 64 * 81);
    int h = blockIdx.y, s0 = blockIdx.x * 64, tid = threadIdx.x;
    for (int idx = tid; idx < 64 * HD; idx += 256) {
        int si = idx / HD, d = idx % HD;
        int s = s0 + si;
        const float* base = qkv + (long)s * (3 * HID) + h * HD;
        float qv = base[d], kv = base[HID + d], vv = base[2 * HID + d];
        float c = cs[s * HD + d], si_ = sn[s * HD + d];
        int dr = (d < HD / 2) ? (d + HD / 2) : (d - HD / 2);
        float sgn = (d < HD / 2) ? -1.f : 1.f;
        sq[si][d] = qv * c + sgn * base[dr] * si_;
        sk[si][d] = kv * c + sgn * base[HID + dr] * si_;
        sv[si][d] = vv;
    }
    __syncthreads();
    for (int idx = tid; idx < 40 * 64; idx += 256) {
        int j = idx >> 6, si = idx & 63;
        long o = ((long)h * 40 + j) * S_LEN + s0 + si;
        Qp[o] = pack_pair(sq[si][2 * j], sq[si][2 * j + 1]);
        Kp[o] = pack_pair(sk[si][2 * j], sk[si][2 * j + 1]);
    }
    for (int idx = tid; idx < 32 * HD; idx += 256) {
        int r = idx / HD, d = idx % HD;
        Vp[((long)h * (S_LEN / 2) + (s0 >> 1) + r) * HD + d] = pack_pair(sv[2 * r][d], sv[2 * r + 1][d]);
    }
}

// ---------------- flash attention (mma.sync bf16x3), plane output ----------------
#define QSTR 68
#define VSTR 84
#define ATT_SMEM ((40 * QSTR * 2 + 32 * VSTR) * (int)sizeof(uint2))

__device__ __forceinline__ void mma_bf16(float c[4], uint32_t a0, uint32_t a1,
                                         uint32_t a2, uint32_t a3, uint32_t b0, uint32_t b1) {
    asm volatile(
        "mma.sync.aligned.m16n8k16.row.col.f32.bf16.bf16.f32 "
        "{%0,%1,%2,%3}, {%4,%5,%6,%7}, {%8,%9}, {%0,%1,%2,%3};"
        : "+f"(c[0]), "+f"(c[1]), "+f"(c[2]), "+f"(c[3])
        : "r"(a0), "r"(a1), "r"(a2), "r"(a3), "r"(b0), "r"(b1));
}

__global__ void __launch_bounds__(128) attn_mma_k(const uint2* __restrict__ Qp,
                                                  const uint2* __restrict__ Kp,
                                                  const uint2* __restrict__ Vp,
                                                  const float* __restrict__ mask,
                                                  int windowed,
                                                  __nv_bfloat16* __restrict__ Ob,
                                                  __nv_bfloat16* __restrict__ Os) {
    extern __shared__ uint2 smu[];
    uint2 (*Qs)[QSTR] = (uint2(*)[QSTR])smu;
    uint2 (*Ks)[QSTR] = (uint2(*)[QSTR])(smu + 40 * QSTR);
    uint2 (*Vs)[VSTR] = (uint2(*)[VSTR])(smu + 2 * 40 * QSTR);
    int h = blockIdx.y, q0 = blockIdx.x * 64, tid = threadIdx.x;
    int w = tid >> 5, lane = tid & 31, g = lane >> 2, tg = lane & 3;

    for (int idx = tid; idx < 40 * 64; idx += 128) {
        int p = idx >> 6, c = idx & 63;
        Qs[p][c] = Qp[((long)h * 40 + p) * S_LEN + q0 + c];
    }
    float O[10][4];
#pragma unroll
    for (int ni = 0; ni < 10; ++ni) { O[ni][0] = O[ni][1] = O[ni][2] = O[ni][3] = 0.f; }
    float m0 = -3.0e38f, m1 = -3.0e38f, l0 = 0.f, l1 = 0.f;
    const float scale = 0.11180339887498949f;
    const float NEG = -3.0e38f;
    int qa = q0 + w * 16 + g;
    int kvs = windowed ? q0 : 0;
    int kve = windowed ? q0 + 64 : S_LEN;

    for (int kv0 = kvs; kv0 < kve; kv0 += 64) {
        __syncthreads();
        for (int idx = tid; idx < 40 * 64; idx += 128) {
            int p = idx >> 6, c = idx & 63;
            Ks[p][c] = Kp[((long)h * 40 + p) * S_LEN + kv0 + c];
        }
        for (int idx = tid; idx < 32 * HD; idx += 128) {
            int r = idx / HD, d = idx % HD;
            Vs[r][d] = Vp[((long)h * (S_LEN / 2) + (kv0 >> 1) + r) * HD + d];
        }
        __syncthreads();

        float s[8][4];
#pragma unroll
        for (int ni = 0; ni < 8; ++ni) { s[ni][0] = s[ni][1] = s[ni][2] = s[ni][3] = 0.f; }
#pragma unroll
        for (int ch = 0; ch < 5; ++ch) {
            int c8 = ch * 8;
            uint2 a0 = Qs[c8 + tg][w * 16 + g];
            uint2 a1 = Qs[c8 + tg][w * 16 + g + 8];
            uint2 a2 = Qs[c8 + 4 + tg][w * 16 + g];
            uint2 a3 = Qs[c8 + 4 + tg][w * 16 + g + 8];
#pragma unroll
            for (int ni = 0; ni < 8; ++ni) {
                uint2 b0 = Ks[c8 + tg][ni * 8 + g];
                uint2 b1 = Ks[c8 + 4 + tg][ni * 8 + g];
                mma_bf16(s[ni], a0.x, a1.x, a2.x, a3.x, b0.x, b1.x);
                mma_bf16(s[ni], a0.x, a1.x, a2.x, a3.x, b0.y, b1.y);
                mma_bf16(s[ni], a0.y, a1.y, a2.y, a3.y, b0.x, b1.x);
            }
        }
#pragma unroll
        for (int ni = 0; ni < 8; ++ni) {
            int col2 = ni * 8 + 2 * tg;
            float2 ma, mb;
            if (windowed) {
                const float* mb_ = mask + ((long)(q0 >> 6) * 64 + (w * 16 + g)) * 64;
                ma = *(const float2*)(mb_ + col2);
                mb = *(const float2*)(mb_ + 8 * 64 + col2);
            } else {
                ma = *(const float2*)(mask + (long)qa * S_LEN + kv0 + col2);
                mb = *(const float2*)(mask + (long)(qa + 8) * S_LEN + kv0 + col2);
            }
            s[ni][0] = s[ni][0] * scale + (1.f - ma.x) * NEG;
            s[ni][1] = s[ni][1] * scale + (1.f - ma.y) * NEG;
            s[ni][2] = s[ni][2] * scale + (1.f - mb.x) * NEG;
            s[ni][3] = s[ni][3] * scale + (1.f - mb.y) * NEG;
        }
        float t0 = -3.0e38f, t1 = -3.0e38f;
#pragma unroll
        for (int ni = 0; ni < 8; ++ni) {
            t0 = fmaxf(t0, fmaxf(s[ni][0], s[ni][1]));
            t1 = fmaxf(t1, fmaxf(s[ni][2], s[ni][3]));
        }
        t0 = fmaxf(t0, __shfl_xor_sync(0xffffffffu, t0, 1));
        t0 = fmaxf(t0, __shfl_xor_sync(0xffffffffu, t0, 2));
        t1 = fmaxf(t1, __shfl_xor_sync(0xffffffffu, t1, 1));
        t1 = fmaxf(t1, __shfl_xor_sync(0xffffffffu, t1, 2));
        float mn0 = fmaxf(m0, t0), mn1 = fmaxf(m1, t1);
        float corr0 = __expf(m0 - mn0), corr1 = __expf(m1 - mn1);
#pragma unroll
        for (int ni = 0; ni < 10; ++ni) {
            O[ni][0] *= corr0; O[ni][1] *= corr0;
            O[ni][2] *= corr1; O[ni][3] *= corr1;
        }
        float sum0 = 0.f, sum1 = 0.f;
#pragma unroll
        for (int ni = 0; ni < 8; ++ni) {
            s[ni][0] = __expf(s[ni][0] - mn0);
            s[ni][1] = __expf(s[ni][1] - mn0);
            s[ni][2] = __expf(s[ni][2] - mn1);
            s[ni][3] = __expf(s[ni][3] - mn1);
            sum0 += s[ni][0] + s[ni][1];
            sum1 += s[ni][2] + s[ni][3];
        }
        sum0 += __shfl_xor_sync(0xffffffffu, sum0, 1);
        sum0 += __shfl_xor_sync(0xffffffffu, sum0, 2);
        sum1 += __shfl_xor_sync(0xffffffffu, sum1, 1);
        sum1 += __shfl_xor_sync(0xffffffffu, sum1, 2);
        l0 = l0 * corr0 + sum0;
        l1 = l1 * corr1 + sum1;
        m0 = mn0; m1 = mn1;
#pragma unroll
        for (int ck = 0; ck < 4; ++ck) {
            uint2 p00 = pack_pair(s[2 * ck][0], s[2 * ck][1]);
            uint2 p01 = pack_pair(s[2 * ck][2], s[2 * ck][3]);
            uint2 p10 = pack_pair(s[2 * ck + 1][0], s[2 * ck + 1][1]);
            uint2 p11 = pack_pair(s[2 * ck + 1][2], s[2 * ck + 1][3]);
#pragma unroll
            for (int ni = 0; ni < 10; ++ni) {
                uint2 b0 = Vs[ck * 8 + tg][ni * 8 + g];
                uint2 b1 = Vs[ck * 8 + 4 + tg][ni * 8 + g];
                mma_bf16(O[ni], p00.x, p01.x, p10.x, p11.x, b0.x, b1.x);
                mma_bf16(O[ni], p00.x, p01.x, p10.x, p11.x, b0.y, b1.y);
                mma_bf16(O[ni], p00.y, p01.y, p10.y, p11.y, b0.x, b1.x);
            }
        }
    }
    float invl0 = 1.f / l0, invl1 = 1.f / l1;
#pragma unroll
    for (int ni = 0; ni < 10; ++ni) {
        int col = h * HD + ni * 8 + 2 * tg;
        store_plane2(Ob, Os, (long)qa * HID + col, O[ni][0] * invl0, O[ni][1] * invl0);
        store_plane2(Ob, Os, (long)(qa + 8) * HID + col, O[ni][2] * invl1, O[ni][3] * invl1);
    }
}

// ---------------- persistent plane GEMM: ldmatrix + mma.sync bf16x3 ----------------
// EPI: 0 none, 2 GELU, 3 +=res, 5 fused silu(gate)*up (interleaved cols) PACK.
#define RSTR 80
#define MAXCTAS 296

__device__ __forceinline__ void cp16(uint32_t dst, const void* src, int sz) {
    asm volatile("cp.async.cg.shared.global [%0], [%1], 16, %2;" :: "r"(dst), "l"(src), "r"(sz));
}
__device__ __forceinline__ void cp_commit() { asm volatile("cp.async.commit_group;" ::: "memory"); }
__device__ __forceinline__ void cp_wait1()  { asm volatile("cp.async.wait_group 1;" ::: "memory"); }

__device__ __forceinline__ void ldsm4(uint32_t& r0, uint32_t& r1, uint32_t& r2, uint32_t& r3,
                                      uint32_t addr) {
    asm volatile("ldmatrix.sync.aligned.m8n8.x4.shared.b16 {%0,%1,%2,%3}, [%4];"
                 : "=r"(r0), "=r"(r1), "=r"(r2), "=r"(r3) : "r"(addr));
}

template <int EPI, bool PACK, int BM>
__global__ void __launch_bounds__(256, 2) pgemm_k(
    const __nv_bfloat16* __restrict__ Apb, const __nv_bfloat16* __restrict__ Aps,
    const __nv_bfloat16* __restrict__ Wpb, const __nv_bfloat16* __restrict__ Wps,
    const float* __restrict__ bias, const float* __restrict__ bias2,
    const float* __restrict__ res,
    float* __restrict__ Cf, __nv_bfloat16* __restrict__ Cb, __nv_bfloat16* __restrict__ Cs,
    int M, int N, int K, int lda, int ldw, int ldc) {
    constexpr int ATILE = BM * RSTR;
    constexpr int BTILE = 128 * RSTR;
    constexpr int STAGE = 2 * ATILE + 2 * BTILE;
    constexpr int MI = BM / 32;
    constexpr int NCP = (2 * BM + 256) * 4;

    extern __shared__ char dsm[];
    uint32_t base = (uint32_t)__cvta_generic_to_shared(dsm);

    int tid = threadIdx.x;
    int lane = tid & 31;
    int warp = tid >> 5;
    int warpM = warp & 1;
    int warpN = warp >> 1;
    int g = lane >> 2;
    int tg = lane & 3;

    int gx = (N + 127) / 128;
    int ntiles = gx * (M / BM);
    int ntile = (K + 31) / 32;

    for (int tile = blockIdx.x; tile < ntiles; tile += gridDim.x) {
        int bmBase = (tile / gx) * BM;
        int bnBase = (tile % gx) * 128;

        float acc[MI][4][4];
#pragma unroll
        for (int mi = 0; mi < MI; ++mi)
#pragma unroll
            for (int ni = 0; ni < 4; ++ni)
#pragma unroll
                for (int r = 0; r < 4; ++r) acc[mi][ni][r] = 0.f;

        auto stage_fn = [&](int t, int s) {
            int k0 = t * 32;
            uint32_t sb = base + s * STAGE;
#pragma unroll
            for (int u = tid; u < NCP; u += 256) {
                int ru = u >> 2, c = u & 3;
                int kb = k0 + c * 8;
                int sz = 2 * (K - kb);
                sz = sz < 0 ? 0 : (sz > 16 ? 16 : sz);
                uint32_t dst;
                const __nv_bfloat16* src;
                if (ru < BM) {
                    dst = sb + ru * RSTR + c * 16;
                    src = Apb + (long)(bmBase + ru) * lda + kb;
                } else if (ru < 2 * BM) {
                    int r = ru - BM;
                    dst = sb + ATILE + r * RSTR + c * 16;
                    src = Aps + (long)(bmBase + r) * lda + kb;
                } else if (ru < 2 * BM + 128) {
                    int r = ru - 2 * BM;
                    dst = sb + 2 * ATILE + r * RSTR + c * 16;
                    src = Wpb + (long)(bnBase + r) * ldw + kb;
                    if (bnBase + r >= N) sz = 0;
                } else {
                    int r = ru - 2 * BM - 128;
                    dst = sb + 2 * ATILE + BTILE + r * RSTR + c * 16;
                    src = Wps + (long)(bnBase + r) * ldw + kb;
                    if (bnBase + r >= N) sz = 0;
                }
                cp16(dst, src, sz);
            }
        };

        stage_fn(0, 0);
        cp_commit();
        if (ntile > 1) stage_fn(1, 1);
        cp_commit();

        for (int t = 0; t < ntile; ++t) {
            cp_wait1();
            __syncthreads();
            uint32_t sb = base + (t & 1) * STAGE;

#pragma unroll
            for (int kc = 0; kc < 2; ++kc) {
                uint32_t bb[4][2], bs[4][2];
                {
                    uint32_t brow_lo = (uint32_t)(warpN * 32 + ((lane >> 4) << 3) + (lane & 7));
                    uint32_t koffB = (uint32_t)(kc * 32 + (((lane >> 3) & 1) << 4));
#pragma unroll
                    for (int p = 0; p < 2; ++p) {
                        uint32_t off = (brow_lo + p * 16) * RSTR + koffB;
                        ldsm4(bb[2 * p][0], bb[2 * p][1], bb[2 * p + 1][0], bb[2 * p + 1][1],
                              sb + 2 * ATILE + off);
                        ldsm4(bs[2 * p][0], bs[2 * p][1], bs[2 * p + 1][0], bs[2 * p + 1][1],
                              sb + 2 * ATILE + BTILE + off);
                    }
                }
                uint32_t aoffc = (uint32_t)(kc * 32 + ((lane >> 4) << 4));
                // mi pairs, term-major: same-acc MMA distance = 8
#pragma unroll
                for (int mp = 0; mp < MI; mp += 2) {
                    uint32_t a[2][4];
#pragma unroll
                    for (int q = 0; q < 2; ++q) {
                        uint32_t arow = (uint32_t)(warpM * (BM / 2) + (mp + q) * 16 + (lane & 15));
                        ldsm4(a[q][0], a[q][1], a[q][2], a[q][3], sb + arow * RSTR + aoffc);
                    }
#pragma unroll
                    for (int q = 0; q < 2; ++q)
#pragma unroll
                        for (int ni = 0; ni < 4; ++ni)
                            mma_bf16(acc[mp + q][ni], a[q][0], a[q][1], a[q][2], a[q][3],
                                     bb[ni][0], bb[ni][1]);
#pragma unroll
                    for (int q = 0; q < 2; ++q)
#pragma unroll
                        for (int ni = 0; ni < 4; ++ni)
                            mma_bf16(acc[mp + q][ni], a[q][0], a[q][1], a[q][2], a[q][3],
                                     bs[ni][0], bs[ni][1]);
                    // reload small-plane A frags into same regs
#pragma unroll
                    for (int q = 0; q < 2; ++q) {
                        uint32_t arow = (uint32_t)(warpM * (BM / 2) + (mp + q) * 16 + (lane & 15));
                        ldsm4(a[q][0], a[q][1], a[q][2], a[q][3], sb + ATILE + arow * RSTR + aoffc);
                    }
#pragma unroll
                    for (int q = 0; q < 2; ++q)
#pragma unroll
                        for (int ni = 0; ni < 4; ++ni)
                            mma_bf16(acc[mp + q][ni], a[q][0], a[q][1], a[q][2], a[q][3],
                                     bb[ni][0], bb[ni][1]);
                }
            }
            __syncthreads();
            if (t + 2 < ntile) stage_fn(t + 2, t & 1);
            cp_commit();
        }

        // ---- epilogue ----
#pragma unroll
        for (int mi = 0; mi < MI; ++mi) {
            int row0 = bmBase + warpM * (BM / 2) + mi * 16 + g;
#pragma unroll
            for (int ni = 0; ni < 4; ++ni) {
                int col = bnBase + warpN * 32 + ni * 8 + 2 * tg;
                if (col >= N) continue;
#pragma unroll
                for (int rh = 0; rh < 2; ++rh) {
                    int row = row0 + rh * 8;
                    float v0 = acc[mi][ni][rh * 2 + 0];
                    float v1 = acc[mi][ni][rh * 2 + 1];
                    if (EPI == 5) {
                        int j = col >> 1;
                        float gv = v0 + bias[j];
                        float uv = v1 + bias2[j];
                        float r = (gv / (1.f + expf(-gv))) * uv;
                        uint16_t b, s;
                        split_bf16(r, b, s);
                        Cb[(long)row * ldc + j] = *(__nv_bfloat16*)&b;
                        Cs[(long)row * ldc + j] = *(__nv_bfloat16*)&s;
                    } else {
                        v0 += bias[col];
                        v1 += bias[col + 1];
                        if (EPI == 2) {
                            v0 = 0.5f * v0 * (1.f + erff(v0 * 0.70710678118654752f));
                            v1 = 0.5f * v1 * (1.f + erff(v1 * 0.70710678118654752f));
                        } else if (EPI == 3) {
                            v0 += res[(long)row * N + col];
                            v1 += res[(long)row * N + col + 1];
                        }
                        if (PACK) store_plane2(Cb, Cs, (long)row * ldc + col, v0, v1);
                        else *(float2*)(Cf + (long)row * ldc + col) = make_float2(v0, v1);
                    }
                }
            }
        }
        __syncthreads();
    }
}

// ---------------- host ----------------
template <int EPI, bool PACK>
static void launch_pg(const __nv_bfloat16* Ab, const __nv_bfloat16* As,
                      const __nv_bfloat16* Wb, const __nv_bfloat16* Ws,
                      const float* bias, const float* bias2, const float* res,
                      float* Cf, __nv_bfloat16* Cb, __nv_bfloat16* Cs,
                      int M, int N, int K, int lda, int ldw, int ldc) {
    int gx = (N + 127) / 128;
    int t128 = gx * (M / 128);
    if (t128 < MAXCTAS && (M % 64) == 0) {
        int nt = gx * (M / 64);
        int grid = nt < MAXCTAS ? nt : MAXCTAS;
        constexpr int SM = 2 * (2 * 64 * RSTR + 2 * 128 * RSTR);
        cudaFuncSetAttribute(pgemm_k<EPI, PACK, 64>,
                             cudaFuncAttributeMaxDynamicSharedMemorySize, SM);
        pgemm_k<EPI, PACK, 64><<<grid, 256, SM>>>(
            Ab, As, Wb, Ws, bias, bias2, res, Cf, Cb, Cs, M, N, K, lda, ldw, ldc);
    } else {
        int grid = t128 < MAXCTAS ? t128 : MAXCTAS;
        constexpr int SM = 2 * (2 * 128 * RSTR + 2 * 128 * RSTR);
        cudaFuncSetAttribute(pgemm_k<EPI, PACK, 128>,
                             cudaFuncAttributeMaxDynamicSharedMemorySize, SM);
        pgemm_k<EPI, PACK, 128><<<grid, 256, SM>>>(
            Ab, As, Wb, Ws, bias, bias2, res, Cf, Cb, Cs, M, N, K, lda, ldw, ldc);
    }
}

static inline void convT(const float* W, __nv_bfloat16* outB, __nv_bfloat16* outS,
                         int K, int N, int L, int ldw) {
    dim3 grid((N + 31) / 32, (K + 31) / 32, L);
    convT_k<<<grid, 256>>>(W, outB, outS, K, N, ldw);
}

#define SYM(p, g) cudaGetSymbolAddress((void**)&p, g)

extern "C" void kernel_launch(void* const* d_in, const int* in_sizes, int n_in,
                              void* d_out, int out_size) {
    const float* in_hs   = (const float*)d_in[0];
    const float* fmask   = (const float*)d_in[1];
    const float* wmask   = (const float*)d_in[2];
    const float* cosd    = (const float*)d_in[3];
    const float* sind    = (const float*)d_in[4];
    const float* norm1_w = (const float*)d_in[5];
    const float* norm2_w = (const float*)d_in[6];
    const float* qkv_w   = (const float*)d_in[7];
    const float* qkv_b   = (const float*)d_in[8];
    const float* proj_w  = (const float*)d_in[9];
    const float* proj_b  = (const float*)d_in[10];
    const float* gate_w  = (const float*)d_in[11];
    const float* gate_b  = (const float*)d_in[12];
    const float* up_w    = (const float*)d_in[13];
    const float* up_b    = (const float*)d_in[14];
    const float* down_w  = (const float*)d_in[15];
    const float* down_b  = (const float*)d_in[16];
    const float* ln_q_w  = (const float*)d_in[17];
    const float* fc1_w   = (const float*)d_in[18];
    const float* fc1_b   = (const float*)d_in[19];
    const float* fc2_w   = (const float*)d_in[20];
    const float* fc2_b   = (const float*)d_in[21];
    float* out = (float*)d_out;

    float *hs, *qkv;
    __nv_bfloat16 *wqkvB, *wqkvS, *wprojB, *wprojS, *wguB, *wguS;
    __nv_bfloat16 *wdownB, *wdownS, *wfc1B, *wfc1S, *wfc2B, *wfc2S;
    __nv_bfloat16 *xB, *xS, *aB, *aS, *gB, *gS;
    uint2 *qp, *kp, *vp;
    SYM(hs, g_hs); SYM(qkv, g_qkv);
    SYM(wqkvB, g_wqkvB); SYM(wqkvS, g_wqkvS);
    SYM(wprojB, g_wprojB); SYM(wprojS, g_wprojS);
    SYM(wguB, g_wguB); SYM(wguS, g_wguS);
    SYM(wdownB, g_wdownB); SYM(wdownS, g_wdownS);
    SYM(wfc1B, g_wfc1B); SYM(wfc1S, g_wfc1S);
    SYM(wfc2B, g_wfc2B); SYM(wfc2S, g_wfc2S);
    SYM(xB, g_xB); SYM(xS, g_xS); SYM(aB, g_aB); SYM(aS, g_aS);
    SYM(gB, g_gB); SYM(gS, g_gS);
    SYM(qp, g_qp); SYM(kp, g_kp); SYM(vp, g_vp);

    const int ROPE_SMEM = 3 * 64 * 81 * (int)sizeof(float);
    cudaFuncSetAttribute(rope_pack_k, cudaFuncAttributeMaxDynamicSharedMemorySize, ROPE_SMEM);
    cudaFuncSetAttribute(attn_mma_k, cudaFuncAttributeMaxDynamicSharedMemorySize, ATT_SMEM);

    // 1 convT qkv, 2 rmsnorm(in_hs), 3 convT proj, 4 = qkv GEMM (ncu capture)
    convT(qkv_w, wqkvB, wqkvS, HID, 3 * HID, NLAYER, HID);
    rmsnorm_plane_k<false><<<S_LEN / 8, 256>>>(in_hs, norm1_w, xB, xS);
    convT(proj_w, wprojB, wprojS, HID, HID, NLAYER, HID);
    launch_pg<0, false>(xB, xS, wqkvB, wqkvS, qkv_b, nullptr, nullptr,
                        qkv, nullptr, nullptr, S_LEN, 3 * HID, HID, HID, HID, 3 * HID);
    {
        dim3 grid((INTER + 31) / 32, (HID + 31) / 32, NLAYER);
        convT2_k<<<grid, 256>>>(gate_w, up_w, wguB, wguS);
    }
    convT(down_w, wdownB, wdownS, INTER, HID, NLAYER, INTERP);
    convT(fc1_w, wfc1B, wfc1S, MERGED, MERGED, 1, MERGED);
    convT(fc2_w, wfc2B, wfc2S, MERGED, OUTDIM, 1, MERGED);

    for (int i = 0; i < NLAYER; ++i) {
        int full = (i == 3 || i == 7) ? 1 : 0;
        if (i > 0) {
            rmsnorm_plane_k<false><<<S_LEN / 8, 256>>>(hs, norm1_w + (long)i * HID, xB, xS);
            launch_pg<0, false>(xB, xS, wqkvB + (long)i * 3840 * HID, wqkvS + (long)i * 3840 * HID,
                                qkv_b + (long)i * 3 * HID, nullptr, nullptr,
                                qkv, nullptr, nullptr, S_LEN, 3 * HID, HID, HID, HID, 3 * HID);
        }
        rope_pack_k<<<dim3(S_LEN / 64, NH), 256, ROPE_SMEM>>>(qkv, cosd, sind, qp, kp, vp);
        attn_mma_k<<<dim3(S_LEN / 64, NH), 128, ATT_SMEM>>>(
            qp, kp, vp, full ? fmask : wmask, full ? 0 : 1, aB, aS);
        // layer 0: residual comes from the input tensor (no copy kernel needed)
        launch_pg<3, false>(aB, aS, wprojB + (long)i * HID * HID, wprojS + (long)i * HID * HID,
                            proj_b + (long)i * HID, nullptr, (i == 0) ? in_hs : hs,
                            hs, nullptr, nullptr, S_LEN, HID, HID, HID, HID, HID);
        rmsnorm_plane_k<false><<<S_LEN / 8, 256>>>(hs, norm2_w + (long)i * HID, xB, xS);
        launch_pg<5, true>(xB, xS, wguB + (long)i * 2 * INTER * HID, wguS + (long)i * 2 * INTER * HID,
                           gate_b + (long)i * INTER, up_b + (long)i * INTER, nullptr,
                           nullptr, gB, gS, S_LEN, 2 * INTER, HID, HID, HID, INTERP);
        launch_pg<3, false>(gB, gS, wdownB + (long)i * HID * INTERP, wdownS + (long)i * HID * INTERP,
                            down_b + (long)i * HID, nullptr, hs,
                            hs, nullptr, nullptr, S_LEN, HID, INTER, INTERP, INTERP, HID);
    }

    // patch merger
    rmsnorm_plane_k<true><<<S_LEN / 8, 256>>>(hs, ln_q_w, xB, xS);
    launch_pg<2, true>(xB, xS, wfc1B, wfc1S, fc1_b, nullptr, nullptr,
                       nullptr, aB, aS, MTOK, MERGED, MERGED, MERGED, MERGED, MERGED);
    launch_pg<0, false>(aB, aS, wfc2B, wfc2S, fc2_b, nullptr, nullptr,
                        out, nullptr, nullptr, MTOK, OUTDIM, MERGED, MERGED, MERGED, OUTDIM);
}

// round 16
// speedup vs baseline: 1.0153x; 1.0153x over previous
#include <cuda_runtime.h>
#include <cuda_bf16.h>
#include <math.h>
#include <stdint.h>

#define S_LEN 2048
#define HID 1280
#define NH 16
#define HD 80
#define INTER 3420
#define INTERP 3424
#define NLAYER 8
#define MERGED 5120
#define OUTDIM 3584
#define MTOK 512

// ---------------- scratch ----------------
__device__ float g_hs[S_LEN * HID];
__device__ float g_qkv[S_LEN * 3 * HID];
__device__ __nv_bfloat16 g_wqkvB[NLAYER * 3840 * HID], g_wqkvS[NLAYER * 3840 * HID];
__device__ __nv_bfloat16 g_wprojB[NLAYER * HID * HID], g_wprojS[NLAYER * HID * HID];
__device__ __nv_bfloat16 g_wguB[NLAYER * 2 * INTER * HID], g_wguS[NLAYER * 2 * INTER * HID];
__device__ __nv_bfloat16 g_wdownB[NLAYER * HID * INTERP], g_wdownS[NLAYER * HID * INTERP];
__device__ __nv_bfloat16 g_wfc1B[MERGED * MERGED], g_wfc1S[MERGED * MERGED];
__device__ __nv_bfloat16 g_wfc2B[OUTDIM * MERGED], g_wfc2S[OUTDIM * MERGED];
__device__ __nv_bfloat16 g_xB[S_LEN * HID], g_xS[S_LEN * HID];
__device__ __nv_bfloat16 g_aB[S_LEN * HID], g_aS[S_LEN * HID];
__device__ __nv_bfloat16 g_gB[S_LEN * INTERP], g_gS[S_LEN * INTERP];
__device__ uint2 g_qp[NH * 40 * S_LEN], g_kp[NH * 40 * S_LEN], g_vp[NH * (S_LEN / 2) * HD];

// ---------------- helpers ----------------
__device__ __forceinline__ void split_bf16(float x, uint16_t& b, uint16_t& s) {
    __nv_bfloat16 hb = __float2bfloat16(x);
    float r = x - __bfloat162float(hb);
    __nv_bfloat16 hs = __float2bfloat16(r);
    b = *(uint16_t*)&hb; s = *(uint16_t*)&hs;
}
__device__ __forceinline__ uint2 pack_pair(float lo, float hi) {
    uint16_t bl, sl, bh, sh;
    split_bf16(lo, bl, sl); split_bf16(hi, bh, sh);
    return make_uint2((uint32_t)bl | ((uint32_t)bh << 16), (uint32_t)sl | ((uint32_t)sh << 16));
}
__device__ __forceinline__ void store_plane2(__nv_bfloat16* B, __nv_bfloat16* S,
                                             long off, float v0, float v1) {
    uint16_t b0, s0, b1, s1;
    split_bf16(v0, b0, s0); split_bf16(v1, b1, s1);
    *(uint32_t*)(B + off) = (uint32_t)b0 | ((uint32_t)b1 << 16);
    *(uint32_t*)(S + off) = (uint32_t)s0 | ((uint32_t)s1 << 16);
}

// ---------------- elementwise ----------------
// W[L][K][N] fp32 -> planes [L][N][ldw] bf16 (transpose), uint32 writes
__global__ void __launch_bounds__(256) convT_k(const float* __restrict__ W,
                                               __nv_bfloat16* __restrict__ outB,
                                               __nv_bfloat16* __restrict__ outS,
                                               int K, int N, int ldw) {
    __shared__ float tile[32][33];
    int l = blockIdx.z;
    const float* Wl = W + (long)l * K * N;
    long obase = (long)l * N * ldw;
    int n0 = blockIdx.x * 32, k0 = blockIdx.y * 32;
    int tx = threadIdx.x & 31, ty = threadIdx.x >> 5;
    for (int i = ty; i < 32; i += 8) {
        int k = k0 + i, n = n0 + tx;
        tile[i][tx] = (k < K && n < N) ? Wl[(long)k * N + n] : 0.f;
    }
    __syncthreads();
    int kp = threadIdx.x & 15, nr = threadIdx.x >> 4;
#pragma unroll
    for (int pass = 0; pass < 2; ++pass) {
        int i = nr + pass * 16;
        int n = n0 + i, k = k0 + 2 * kp;
        if (n < N && k < K) {
            uint16_t b0, s0, b1, s1;
            split_bf16(tile[2 * kp][i], b0, s0);
            split_bf16(tile[2 * kp + 1][i], b1, s1);
            *(uint32_t*)(outB + obase + (long)n * ldw + k) = (uint32_t)b0 | ((uint32_t)b1 << 16);
            *(uint32_t*)(outS + obase + (long)n * ldw + k) = (uint32_t)s0 | ((uint32_t)s1 << 16);
        }
    }
}

// gate/up interleaved: out row 2j = gate col j, row 2j+1 = up col j
__global__ void __launch_bounds__(256) convT2_k(const float* __restrict__ Wg,
                                                const float* __restrict__ Wu,
                                                __nv_bfloat16* __restrict__ outB,
                                                __nv_bfloat16* __restrict__ outS) {
    __shared__ float tg_[32][33];
    __shared__ float tu_[32][33];
    int l = blockIdx.z;
    const float* Wgl = Wg + (long)l * HID * INTER;
    const float* Wul = Wu + (long)l * HID * INTER;
    long obase = (long)l * 2 * INTER * HID;
    int n0 = blockIdx.x * 32, k0 = blockIdx.y * 32;
    int tx = threadIdx.x & 31, ty = threadIdx.x >> 5;
    for (int i = ty; i < 32; i += 8) {
        int k = k0 + i, n = n0 + tx;
        float gv = (k < HID && n < INTER) ? Wgl[(long)k * INTER + n] : 0.f;
        float uv = (k < HID && n < INTER) ? Wul[(long)k * INTER + n] : 0.f;
        tg_[i][tx] = gv; tu_[i][tx] = uv;
    }
    __syncthreads();
    int kp = threadIdx.x & 15, nr = threadIdx.x >> 4;
#pragma unroll
    for (int pass = 0; pass < 2; ++pass) {
        int i = nr + pass * 16;
        int n = n0 + i, k = k0 + 2 * kp;
        if (n < INTER && k < HID) {
            uint16_t b0, s0, b1, s1;
            split_bf16(tg_[2 * kp][i], b0, s0);
            split_bf16(tg_[2 * kp + 1][i], b1, s1);
            *(uint32_t*)(outB + obase + (long)(2 * n) * HID + k) = (uint32_t)b0 | ((uint32_t)b1 << 16);
            *(uint32_t*)(outS + obase + (long)(2 * n) * HID + k) = (uint32_t)s0 | ((uint32_t)s1 << 16);
            split_bf16(tu_[2 * kp][i], b0, s0);
            split_bf16(tu_[2 * kp + 1][i], b1, s1);
            *(uint32_t*)(outB + obase + (long)(2 * n + 1) * HID + k) = (uint32_t)b0 | ((uint32_t)b1 << 16);
            *(uint32_t*)(outS + obase + (long)(2 * n + 1) * HID + k) = (uint32_t)s0 | ((uint32_t)s1 << 16);
        }
    }
}

// warp-per-row rmsnorm -> planes
template <bool MERGER>
__global__ void __launch_bounds__(256) rmsnorm_plane_k(const float* __restrict__ x,
                                                       const float* __restrict__ w,
                                                       __nv_bfloat16* __restrict__ yB,
                                                       __nv_bfloat16* __restrict__ yS) {
    int row = blockIdx.x * 8 + (threadIdx.x >> 5);
    int lane = threadIdx.x & 31;
    const float* xr = x + (long)row * HID;
    float2 v[20];
    float ss = 0.f;
#pragma unroll
    for (int i = 0; i < 20; ++i) {
        v[i] = *(const float2*)(xr + i * 64 + 2 * lane);
        ss += v[i].x * v[i].x + v[i].y * v[i].y;
    }
#pragma unroll
    for (int o = 16; o > 0; o >>= 1) ss += __shfl_xor_sync(0xffffffffu, ss, o);
    float inv = rsqrtf(ss / (float)HID + 1e-6f);
    long base = MERGER ? ((long)(row >> 2) * MERGED + (row & 3) * HID) : ((long)row * HID);
#pragma unroll
    for (int i = 0; i < 20; ++i) {
        int col = i * 64 + 2 * lane;
        float2 wv = *(const float2*)(w + col);
        store_plane2(yB, yS, base + col, v[i].x * inv * wv.x, v[i].y * inv * wv.y);
    }
}

// rope + pack q,k k-major over d; v pairs over kv
__global__ void __launch_bounds__(256) rope_pack_k(const float* __restrict__ qkv,
                                                   const float* __restrict__ cs,
                                                   const float* __restrict__ sn,
                                                   uint2* __restrict__ Qp,
                                                   uint2* __restrict__ Kp,
                                                   uint2* __restrict__ Vp) {
    extern __shared__ float smf[];
    float (*sq)[81] = (float(*)[81])smf;
    float (*sk)[81] = (float(*)[81])(smf + 64 * 81);
    float (*sv)[81] = (float(*)[81])(smf + 2 * 64 * 81);
    int h = blockIdx.y, s0 = blockIdx.x * 64, tid = threadIdx.x;
    for (int idx = tid; idx < 64 * HD; idx += 256) {
        int si = idx / HD, d = idx % HD;
        int s = s0 + si;
        const float* base = qkv + (long)s * (3 * HID) + h * HD;
        float qv = base[d], kv = base[HID + d], vv = base[2 * HID + d];
        float c = cs[s * HD + d], si_ = sn[s * HD + d];
        int dr = (d < HD / 2) ? (d + HD / 2) : (d - HD / 2);
        float sgn = (d < HD / 2) ? -1.f : 1.f;
        sq[si][d] = qv * c + sgn * base[dr] * si_;
        sk[si][d] = kv * c + sgn * base[HID + dr] * si_;
        sv[si][d] = vv;
    }
    __syncthreads();
    for (int idx = tid; idx < 40 * 64; idx += 256) {
        int j = idx >> 6, si = idx & 63;
        long o = ((long)h * 40 + j) * S_LEN + s0 + si;
        Qp[o] = pack_pair(sq[si][2 * j], sq[si][2 * j + 1]);
        Kp[o] = pack_pair(sk[si][2 * j], sk[si][2 * j + 1]);
    }
    for (int idx = tid; idx < 32 * HD; idx += 256) {
        int r = idx / HD, d = idx % HD;
        Vp[((long)h * (S_LEN / 2) + (s0 >> 1) + r) * HD + d] = pack_pair(sv[2 * r][d], sv[2 * r + 1][d]);
    }
}

// ---------------- flash attention (mma.sync bf16x3), plane output ----------------
#define QSTR 68
#define VSTR 84
#define ATT_SMEM ((40 * QSTR * 2 + 32 * VSTR) * (int)sizeof(uint2))

__device__ __forceinline__ void mma_bf16(float c[4], uint32_t a0, uint32_t a1,
                                         uint32_t a2, uint32_t a3, uint32_t b0, uint32_t b1) {
    asm volatile(
        "mma.sync.aligned.m16n8k16.row.col.f32.bf16.bf16.f32 "
        "{%0,%1,%2,%3}, {%4,%5,%6,%7}, {%8,%9}, {%0,%1,%2,%3};"
        : "+f"(c[0]), "+f"(c[1]), "+f"(c[2]), "+f"(c[3])
        : "r"(a0), "r"(a1), "r"(a2), "r"(a3), "r"(b0), "r"(b1));
}

__global__ void __launch_bounds__(128) attn_mma_k(const uint2* __restrict__ Qp,
                                                  const uint2* __restrict__ Kp,
                                                  const uint2* __restrict__ Vp,
                                                  const float* __restrict__ mask,
                                                  int windowed,
                                                  __nv_bfloat16* __restrict__ Ob,
                                                  __nv_bfloat16* __restrict__ Os) {
    extern __shared__ uint2 smu[];
    uint2 (*Qs)[QSTR] = (uint2(*)[QSTR])smu;
    uint2 (*Ks)[QSTR] = (uint2(*)[QSTR])(smu + 40 * QSTR);
    uint2 (*Vs)[VSTR] = (uint2(*)[VSTR])(smu + 2 * 40 * QSTR);
    int h = blockIdx.y, q0 = blockIdx.x * 64, tid = threadIdx.x;
    int w = tid >> 5, lane = tid & 31, g = lane >> 2, tg = lane & 3;

    for (int idx = tid; idx < 40 * 64; idx += 128) {
        int p = idx >> 6, c = idx & 63;
        Qs[p][c] = Qp[((long)h * 40 + p) * S_LEN + q0 + c];
    }
    float O[10][4];
#pragma unroll
    for (int ni = 0; ni < 10; ++ni) { O[ni][0] = O[ni][1] = O[ni][2] = O[ni][3] = 0.f; }
    float m0 = -3.0e38f, m1 = -3.0e38f, l0 = 0.f, l1 = 0.f;
    const float scale = 0.11180339887498949f;
    const float NEG = -3.0e38f;
    int qa = q0 + w * 16 + g;
    int kvs = windowed ? q0 : 0;
    int kve = windowed ? q0 + 64 : S_LEN;

    for (int kv0 = kvs; kv0 < kve; kv0 += 64) {
        __syncthreads();
        for (int idx = tid; idx < 40 * 64; idx += 128) {
            int p = idx >> 6, c = idx & 63;
            Ks[p][c] = Kp[((long)h * 40 + p) * S_LEN + kv0 + c];
        }
        for (int idx = tid; idx < 32 * HD; idx += 128) {
            int r = idx / HD, d = idx % HD;
            Vs[r][d] = Vp[((long)h * (S_LEN / 2) + (kv0 >> 1) + r) * HD + d];
        }
        __syncthreads();

        float s[8][4];
#pragma unroll
        for (int ni = 0; ni < 8; ++ni) { s[ni][0] = s[ni][1] = s[ni][2] = s[ni][3] = 0.f; }
#pragma unroll
        for (int ch = 0; ch < 5; ++ch) {
            int c8 = ch * 8;
            uint2 a0 = Qs[c8 + tg][w * 16 + g];
            uint2 a1 = Qs[c8 + tg][w * 16 + g + 8];
            uint2 a2 = Qs[c8 + 4 + tg][w * 16 + g];
            uint2 a3 = Qs[c8 + 4 + tg][w * 16 + g + 8];
#pragma unroll
            for (int ni = 0; ni < 8; ++ni) {
                uint2 b0 = Ks[c8 + tg][ni * 8 + g];
                uint2 b1 = Ks[c8 + 4 + tg][ni * 8 + g];
                mma_bf16(s[ni], a0.x, a1.x, a2.x, a3.x, b0.x, b1.x);
                mma_bf16(s[ni], a0.x, a1.x, a2.x, a3.x, b0.y, b1.y);
                mma_bf16(s[ni], a0.y, a1.y, a2.y, a3.y, b0.x, b1.x);
            }
        }
#pragma unroll
        for (int ni = 0; ni < 8; ++ni) {
            int col2 = ni * 8 + 2 * tg;
            float2 ma, mb;
            if (windowed) {
                const float* mb_ = mask + ((long)(q0 >> 6) * 64 + (w * 16 + g)) * 64;
                ma = *(const float2*)(mb_ + col2);
                mb = *(const float2*)(mb_ + 8 * 64 + col2);
            } else {
                ma = *(const float2*)(mask + (long)qa * S_LEN + kv0 + col2);
                mb = *(const float2*)(mask + (long)(qa + 8) * S_LEN + kv0 + col2);
            }
            s[ni][0] = s[ni][0] * scale + (1.f - ma.x) * NEG;
            s[ni][1] = s[ni][1] * scale + (1.f - ma.y) * NEG;
            s[ni][2] = s[ni][2] * scale + (1.f - mb.x) * NEG;
            s[ni][3] = s[ni][3] * scale + (1.f - mb.y) * NEG;
        }
        float t0 = -3.0e38f, t1 = -3.0e38f;
#pragma unroll
        for (int ni = 0; ni < 8; ++ni) {
            t0 = fmaxf(t0, fmaxf(s[ni][0], s[ni][1]));
            t1 = fmaxf(t1, fmaxf(s[ni][2], s[ni][3]));
        }
        t0 = fmaxf(t0, __shfl_xor_sync(0xffffffffu, t0, 1));
        t0 = fmaxf(t0, __shfl_xor_sync(0xffffffffu, t0, 2));
        t1 = fmaxf(t1, __shfl_xor_sync(0xffffffffu, t1, 1));
        t1 = fmaxf(t1, __shfl_xor_sync(0xffffffffu, t1, 2));
        float mn0 = fmaxf(m0, t0), mn1 = fmaxf(m1, t1);
        float corr0 = __expf(m0 - mn0), corr1 = __expf(m1 - mn1);
#pragma unroll
        for (int ni = 0; ni < 10; ++ni) {
            O[ni][0] *= corr0; O[ni][1] *= corr0;
            O[ni][2] *= corr1; O[ni][3] *= corr1;
        }
        float sum0 = 0.f, sum1 = 0.f;
#pragma unroll
        for (int ni = 0; ni < 8; ++ni) {
            s[ni][0] = __expf(s[ni][0] - mn0);
            s[ni][1] = __expf(s[ni][1] - mn0);
            s[ni][2] = __expf(s[ni][2] - mn1);
            s[ni][3] = __expf(s[ni][3] - mn1);
            sum0 += s[ni][0] + s[ni][1];
            sum1 += s[ni][2] + s[ni][3];
        }
        sum0 += __shfl_xor_sync(0xffffffffu, sum0, 1);
        sum0 += __shfl_xor_sync(0xffffffffu, sum0, 2);
        sum1 += __shfl_xor_sync(0xffffffffu, sum1, 1);
        sum1 += __shfl_xor_sync(0xffffffffu, sum1, 2);
        l0 = l0 * corr0 + sum0;
        l1 = l1 * corr1 + sum1;
        m0 = mn0; m1 = mn1;
#pragma unroll
        for (int ck = 0; ck < 4; ++ck) {
            uint2 p00 = pack_pair(s[2 * ck][0], s[2 * ck][1]);
            uint2 p01 = pack_pair(s[2 * ck][2], s[2 * ck][3]);
            uint2 p10 = pack_pair(s[2 * ck + 1][0], s[2 * ck + 1][1]);
            uint2 p11 = pack_pair(s[2 * ck + 1][2], s[2 * ck + 1][3]);
#pragma unroll
            for (int ni = 0; ni < 10; ++ni) {
                uint2 b0 = Vs[ck * 8 + tg][ni * 8 + g];
                uint2 b1 = Vs[ck * 8 + 4 + tg][ni * 8 + g];
                mma_bf16(O[ni], p00.x, p01.x, p10.x, p11.x, b0.x, b1.x);
                mma_bf16(O[ni], p00.x, p01.x, p10.x, p11.x, b0.y, b1.y);
                mma_bf16(O[ni], p00.y, p01.y, p10.y, p11.y, b0.x, b1.x);
            }
        }
    }
    float invl0 = 1.f / l0, invl1 = 1.f / l1;
#pragma unroll
    for (int ni = 0; ni < 10; ++ni) {
        int col = h * HD + ni * 8 + 2 * tg;
        store_plane2(Ob, Os, (long)qa * HID + col, O[ni][0] * invl0, O[ni][1] * invl0);
        store_plane2(Ob, Os, (long)(qa + 8) * HID + col, O[ni][2] * invl1, O[ni][3] * invl1);
    }
}

// ---------------- persistent plane GEMM: ldmatrix + mma.sync bf16x3 ----------------
// EPI: 0 none, 2 GELU, 3 +=res, 5 fused silu(gate)*up (interleaved cols) PACK.
#define RSTR 80
#define MAXCTAS 304

__device__ __forceinline__ void cp16(uint32_t dst, const void* src, int sz) {
    asm volatile("cp.async.cg.shared.global [%0], [%1], 16, %2;" :: "r"(dst), "l"(src), "r"(sz));
}
__device__ __forceinline__ void cp_commit() { asm volatile("cp.async.commit_group;" ::: "memory"); }
__device__ __forceinline__ void cp_wait1()  { asm volatile("cp.async.wait_group 1;" ::: "memory"); }

__device__ __forceinline__ void ldsm4(uint32_t& r0, uint32_t& r1, uint32_t& r2, uint32_t& r3,
                                      uint32_t addr) {
    asm volatile("ldmatrix.sync.aligned.m8n8.x4.shared.b16 {%0,%1,%2,%3}, [%4];"
                 : "=r"(r0), "=r"(r1), "=r"(r2), "=r"(r3) : "r"(addr));
}

template <int EPI, bool PACK, int BM>
__global__ void __launch_bounds__(256, 2) pgemm_k(
    const __nv_bfloat16* __restrict__ Apb, const __nv_bfloat16* __restrict__ Aps,
    const __nv_bfloat16* __restrict__ Wpb, const __nv_bfloat16* __restrict__ Wps,
    const float* __restrict__ bias, const float* __restrict__ bias2,
    const float* __restrict__ res,
    float* __restrict__ Cf, __nv_bfloat16* __restrict__ Cb, __nv_bfloat16* __restrict__ Cs,
    int M, int N, int K, int lda, int ldw, int ldc) {
    constexpr int ATILE = BM * RSTR;
    constexpr int BTILE = 128 * RSTR;
    constexpr int STAGE = 2 * ATILE + 2 * BTILE;
    constexpr int MI = BM / 32;
    constexpr int NCP = (2 * BM + 256) * 4;

    extern __shared__ char dsm[];
    uint32_t base = (uint32_t)__cvta_generic_to_shared(dsm);

    int tid = threadIdx.x;
    int lane = tid & 31;
    int warp = tid >> 5;
    int warpM = warp & 1;
    int warpN = warp >> 1;
    int g = lane >> 2;
    int tg = lane & 3;

    int gx = (N + 127) / 128;
    int ntiles = gx * (M / BM);
    int ntile = (K + 31) / 32;

    for (int tile = blockIdx.x; tile < ntiles; tile += gridDim.x) {
        int bmBase = (tile / gx) * BM;
        int bnBase = (tile % gx) * 128;

        float acc[MI][4][4];
#pragma unroll
        for (int mi = 0; mi < MI; ++mi)
#pragma unroll
            for (int ni = 0; ni < 4; ++ni)
#pragma unroll
                for (int r = 0; r < 4; ++r) acc[mi][ni][r] = 0.f;

        auto stage_fn = [&](int t, int s) {
            int k0 = t * 32;
            uint32_t sb = base + s * STAGE;
#pragma unroll
            for (int u = tid; u < NCP; u += 256) {
                int ru = u >> 2, c = u & 3;
                int kb = k0 + c * 8;
                int sz = 2 * (K - kb);
                sz = sz < 0 ? 0 : (sz > 16 ? 16 : sz);
                uint32_t dst;
                const __nv_bfloat16* src;
                if (ru < BM) {
                    dst = sb + ru * RSTR + c * 16;
                    src = Apb + (long)(bmBase + ru) * lda + kb;
                } else if (ru < 2 * BM) {
                    int r = ru - BM;
                    dst = sb + ATILE + r * RSTR + c * 16;
                    src = Aps + (long)(bmBase + r) * lda + kb;
                } else if (ru < 2 * BM + 128) {
                    int r = ru - 2 * BM;
                    dst = sb + 2 * ATILE + r * RSTR + c * 16;
                    src = Wpb + (long)(bnBase + r) * ldw + kb;
                    if (bnBase + r >= N) sz = 0;
                } else {
                    int r = ru - 2 * BM - 128;
                    dst = sb + 2 * ATILE + BTILE + r * RSTR + c * 16;
                    src = Wps + (long)(bnBase + r) * ldw + kb;
                    if (bnBase + r >= N) sz = 0;
                }
                cp16(dst, src, sz);
            }
        };

        stage_fn(0, 0);
        cp_commit();
        if (ntile > 1) stage_fn(1, 1);
        cp_commit();

        for (int t = 0; t < ntile; ++t) {
            cp_wait1();
            __syncthreads();
            uint32_t sb = base + (t & 1) * STAGE;

#pragma unroll
            for (int kc = 0; kc < 2; ++kc) {
                uint32_t bb[4][2], bs[4][2];
                {
                    uint32_t brow_lo = (uint32_t)(warpN * 32 + ((lane >> 4) << 3) + (lane & 7));
                    uint32_t koffB = (uint32_t)(kc * 32 + (((lane >> 3) & 1) << 4));
#pragma unroll
                    for (int p = 0; p < 2; ++p) {
                        uint32_t off = (brow_lo + p * 16) * RSTR + koffB;
                        ldsm4(bb[2 * p][0], bb[2 * p][1], bb[2 * p + 1][0], bb[2 * p + 1][1],
                              sb + 2 * ATILE + off);
                        ldsm4(bs[2 * p][0], bs[2 * p][1], bs[2 * p + 1][0], bs[2 * p + 1][1],
                              sb + 2 * ATILE + BTILE + off);
                    }
                }
                uint32_t aoffc = (uint32_t)(kc * 32 + ((lane >> 4) << 4));
#pragma unroll
                for (int mi = 0; mi < MI; ++mi) {
                    uint32_t arow = (uint32_t)(warpM * (BM / 2) + mi * 16 + (lane & 15));
                    uint32_t off = arow * RSTR + aoffc;
                    uint32_t a0, a1, a2, a3, s0, s1, s2, s3;
                    ldsm4(a0, a1, a2, a3, sb + off);
                    ldsm4(s0, s1, s2, s3, sb + ATILE + off);
#pragma unroll
                    for (int ni = 0; ni < 4; ++ni)
                        mma_bf16(acc[mi][ni], a0, a1, a2, a3, bb[ni][0], bb[ni][1]);
#pragma unroll
                    for (int ni = 0; ni < 4; ++ni)
                        mma_bf16(acc[mi][ni], a0, a1, a2, a3, bs[ni][0], bs[ni][1]);
#pragma unroll
                    for (int ni = 0; ni < 4; ++ni)
                        mma_bf16(acc[mi][ni], s0, s1, s2, s3, bb[ni][0], bb[ni][1]);
                }
            }
            __syncthreads();
            if (t + 2 < ntile) stage_fn(t + 2, t & 1);
            cp_commit();
        }

        // ---- epilogue ----
#pragma unroll
        for (int mi = 0; mi < MI; ++mi) {
            int row0 = bmBase + warpM * (BM / 2) + mi * 16 + g;
#pragma unroll
            for (int ni = 0; ni < 4; ++ni) {
                int col = bnBase + warpN * 32 + ni * 8 + 2 * tg;
                if (col >= N) continue;
#pragma unroll
                for (int rh = 0; rh < 2; ++rh) {
                    int row = row0 + rh * 8;
                    float v0 = acc[mi][ni][rh * 2 + 0];
                    float v1 = acc[mi][ni][rh * 2 + 1];
                    if (EPI == 5) {
                        int j = col >> 1;
                        float gv = v0 + bias[j];
                        float uv = v1 + bias2[j];
                        float r = (gv / (1.f + expf(-gv))) * uv;
                        uint16_t b, s;
                        split_bf16(r, b, s);
                        Cb[(long)row * ldc + j] = *(__nv_bfloat16*)&b;
                        Cs[(long)row * ldc + j] = *(__nv_bfloat16*)&s;
                    } else {
                        v0 += bias[col];
                        v1 += bias[col + 1];
                        if (EPI == 2) {
                            v0 = 0.5f * v0 * (1.f + erff(v0 * 0.70710678118654752f));
                            v1 = 0.5f * v1 * (1.f + erff(v1 * 0.70710678118654752f));
                        } else if (EPI == 3) {
                            v0 += res[(long)row * N + col];
                            v1 += res[(long)row * N + col + 1];
                        }
                        if (PACK) store_plane2(Cb, Cs, (long)row * ldc + col, v0, v1);
                        else *(float2*)(Cf + (long)row * ldc + col) = make_float2(v0, v1);
                    }
                }
            }
        }
        __syncthreads();
    }
}

// ---------------- host ----------------
template <int EPI, bool PACK>
static void launch_pg(cudaStream_t st,
                      const __nv_bfloat16* Ab, const __nv_bfloat16* As,
                      const __nv_bfloat16* Wb, const __nv_bfloat16* Ws,
                      const float* bias, const float* bias2, const float* res,
                      float* Cf, __nv_bfloat16* Cb, __nv_bfloat16* Cs,
                      int M, int N, int K, int lda, int ldw, int ldc) {
    int gx = (N + 127) / 128;
    int t128 = gx * (M / 128);
    if (t128 < MAXCTAS && (M % 64) == 0) {
        int nt = gx * (M / 64);
        int grid = nt < MAXCTAS ? nt : MAXCTAS;
        constexpr int SM = 2 * (2 * 64 * RSTR + 2 * 128 * RSTR);
        cudaFuncSetAttribute(pgemm_k<EPI, PACK, 64>,
                             cudaFuncAttributeMaxDynamicSharedMemorySize, SM);
        pgemm_k<EPI, PACK, 64><<<grid, 256, SM, st>>>(
            Ab, As, Wb, Ws, bias, bias2, res, Cf, Cb, Cs, M, N, K, lda, ldw, ldc);
    } else {
        int grid = t128 < MAXCTAS ? t128 : MAXCTAS;
        constexpr int SM = 2 * (2 * 128 * RSTR + 2 * 128 * RSTR);
        cudaFuncSetAttribute(pgemm_k<EPI, PACK, 128>,
                             cudaFuncAttributeMaxDynamicSharedMemorySize, SM);
        pgemm_k<EPI, PACK, 128><<<grid, 256, SM, st>>>(
            Ab, As, Wb, Ws, bias, bias2, res, Cf, Cb, Cs, M, N, K, lda, ldw, ldc);
    }
}

static inline void convT(cudaStream_t st, const float* W,
                         __nv_bfloat16* outB, __nv_bfloat16* outS,
                         int K, int N, int L, int ldw) {
    dim3 grid((N + 31) / 32, (K + 31) / 32, L);
    convT_k<<<grid, 256, 0, st>>>(W, outB, outS, K, N, ldw);
}

#define SYM(p, g) cudaGetSymbolAddress((void**)&p, g)

extern "C" void kernel_launch(void* const* d_in, const int* in_sizes, int n_in,
                              void* d_out, int out_size) {
    const float* in_hs   = (const float*)d_in[0];
    const float* fmask   = (const float*)d_in[1];
    const float* wmask   = (const float*)d_in[2];
    const float* cosd    = (const float*)d_in[3];
    const float* sind    = (const float*)d_in[4];
    const float* norm1_w = (const float*)d_in[5];
    const float* norm2_w = (const float*)d_in[6];
    const float* qkv_w   = (const float*)d_in[7];
    const float* qkv_b   = (const float*)d_in[8];
    const float* proj_w  = (const float*)d_in[9];
    const float* proj_b  = (const float*)d_in[10];
    const float* gate_w  = (const float*)d_in[11];
    const float* gate_b  = (const float*)d_in[12];
    const float* up_w    = (const float*)d_in[13];
    const float* up_b    = (const float*)d_in[14];
    const float* down_w  = (const float*)d_in[15];
    const float* down_b  = (const float*)d_in[16];
    const float* ln_q_w  = (const float*)d_in[17];
    const float* fc1_w   = (const float*)d_in[18];
    const float* fc1_b   = (const float*)d_in[19];
    const float* fc2_w   = (const float*)d_in[20];
    const float* fc2_b   = (const float*)d_in[21];
    float* out = (float*)d_out;

    float *hs, *qkv;
    __nv_bfloat16 *wqkvB, *wqkvS, *wprojB, *wprojS, *wguB, *wguS;
    __nv_bfloat16 *wdownB, *wdownS, *wfc1B, *wfc1S, *wfc2B, *wfc2S;
    __nv_bfloat16 *xB, *xS, *aB, *aS, *gB, *gS;
    uint2 *qp, *kp, *vp;
    SYM(hs, g_hs); SYM(qkv, g_qkv);
    SYM(wqkvB, g_wqkvB); SYM(wqkvS, g_wqkvS);
    SYM(wprojB, g_wprojB); SYM(wprojS, g_wprojS);
    SYM(wguB, g_wguB); SYM(wguS, g_wguS);
    SYM(wdownB, g_wdownB); SYM(wdownS, g_wdownS);
    SYM(wfc1B, g_wfc1B); SYM(wfc1S, g_wfc1S);
    SYM(wfc2B, g_wfc2B); SYM(wfc2S, g_wfc2S);
    SYM(xB, g_xB); SYM(xS, g_xS); SYM(aB, g_aB); SYM(aS, g_aS);
    SYM(gB, g_gB); SYM(gS, g_gS);
    SYM(qp, g_qp); SYM(kp, g_kp); SYM(vp, g_vp);

    // static side stream + fork/join events (created on first, uncaptured, call)
    static cudaStream_t s2 = nullptr;
    static cudaEvent_t evFork = nullptr, evJoin = nullptr;
    if (!s2) {
        cudaStreamCreateWithFlags(&s2, cudaStreamNonBlocking);
        cudaEventCreateWithFlags(&evFork, cudaEventDisableTiming);
        cudaEventCreateWithFlags(&evJoin, cudaEventDisableTiming);
    }
    cudaStream_t s0 = 0;

    const int ROPE_SMEM = 3 * 64 * 81 * (int)sizeof(float);
    cudaFuncSetAttribute(rope_pack_k, cudaFuncAttributeMaxDynamicSharedMemorySize, ROPE_SMEM);
    cudaFuncSetAttribute(attn_mma_k, cudaFuncAttributeMaxDynamicSharedMemorySize, ATT_SMEM);

    // stream0: L1 convT qkv, L2 rmsnorm
    convT(s0, qkv_w, wqkvB, wqkvS, HID, 3 * HID, NLAYER, HID);
    rmsnorm_plane_k<false><<<S_LEN / 8, 256, 0, s0>>>(in_hs, norm1_w, xB, xS);
    // fork: side stream converts all remaining weights
    cudaEventRecord(evFork, s0);
    cudaStreamWaitEvent(s2, evFork, 0);
    convT(s2, proj_w, wprojB, wprojS, HID, HID, NLAYER, HID);      // L3
    // L4 on stream0 = qkv GEMM (ncu capture target)
    launch_pg<0, false>(s0, xB, xS, wqkvB, wqkvS, qkv_b, nullptr, nullptr,
                        qkv, nullptr, nullptr, S_LEN, 3 * HID, HID, HID, HID, 3 * HID);
    {
        dim3 grid((INTER + 31) / 32, (HID + 31) / 32, NLAYER);
        convT2_k<<<grid, 256, 0, s2>>>(gate_w, up_w, wguB, wguS);
    }
    convT(s2, down_w, wdownB, wdownS, INTER, HID, NLAYER, INTERP);
    convT(s2, fc1_w, wfc1B, wfc1S, MERGED, MERGED, 1, MERGED);
    convT(s2, fc2_w, wfc2B, wfc2S, MERGED, OUTDIM, 1, MERGED);
    cudaEventRecord(evJoin, s2);

    for (int i = 0; i < NLAYER; ++i) {
        int full = (i == 3 || i == 7) ? 1 : 0;
        if (i > 0) {
            rmsnorm_plane_k<false><<<S_LEN / 8, 256, 0, s0>>>(hs, norm1_w + (long)i * HID, xB, xS);
            launch_pg<0, false>(s0, xB, xS, wqkvB + (long)i * 3840 * HID, wqkvS + (long)i * 3840 * HID,
                                qkv_b + (long)i * 3 * HID, nullptr, nullptr,
                                qkv, nullptr, nullptr, S_LEN, 3 * HID, HID, HID, HID, 3 * HID);
        }
        rope_pack_k<<<dim3(S_LEN / 64, NH), 256, ROPE_SMEM, s0>>>(qkv, cosd, sind, qp, kp, vp);
        attn_mma_k<<<dim3(S_LEN / 64, NH), 128, ATT_SMEM, s0>>>(
            qp, kp, vp, full ? fmask : wmask, full ? 0 : 1, aB, aS);
        if (i == 0) cudaStreamWaitEvent(s0, evJoin, 0);   // join before first weight use from s2
        launch_pg<3, false>(s0, aB, aS, wprojB + (long)i * HID * HID, wprojS + (long)i * HID * HID,
                            proj_b + (long)i * HID, nullptr, (i == 0) ? in_hs : hs,
                            hs, nullptr, nullptr, S_LEN, HID, HID, HID, HID, HID);
        rmsnorm_plane_k<false><<<S_LEN / 8, 256, 0, s0>>>(hs, norm2_w + (long)i * HID, xB, xS);
        launch_pg<5, true>(s0, xB, xS, wguB + (long)i * 2 * INTER * HID, wguS + (long)i * 2 * INTER * HID,
                           gate_b + (long)i * INTER, up_b + (long)i * INTER, nullptr,
                           nullptr, gB, gS, S_LEN, 2 * INTER, HID, HID, HID, INTERP);
        launch_pg<3, false>(s0, gB, gS, wdownB + (long)i * HID * INTERP, wdownS + (long)i * HID * INTERP,
                            down_b + (long)i * HID, nullptr, hs,
                            hs, nullptr, nullptr, S_LEN, HID, INTER, INTERP, INTERP, HID);
    }

    // patch merger
    rmsnorm_plane_k<true><<<S_LEN / 8, 256, 0, s0>>>(hs, ln_q_w, xB, xS);
    launch_pg<2, true>(s0, xB, xS, wfc1B, wfc1S, fc1_b, nullptr, nullptr,
                       nullptr, aB, aS, MTOK, MERGED, MERGED, MERGED, MERGED, MERGED);
    launch_pg<0, false>(s0, aB, aS, wfc2B, wfc2S, fc2_b, nullptr, nullptr,
                        out, nullptr, nullptr, MTOK, OUTDIM, MERGED, MERGED, MERGED, OUTDIM);
}